// round 6
// baseline (speedup 1.0000x reference)
#include <cuda_runtime.h>
#include <cuda_fp16.h>

#define EPSV 1e-8f

constexpr int Bb = 64;
constexpr int N0 = 20000, E0 = 200000, M0 = 8000;
constexpr int E1 = 80000,  M1 = 2000;
constexpr int E2 = 20000,  M2 = 500;
constexpr int ETOT = E0 + E1 + E2;
constexpr int MTOT = M0 + M1 + M2;

constexpr int NB = 592;                 // 4 CTAs/SM x 148 SMs -> exactly wave-1 resident
constexpr int NT = 256;
constexpr int NW = NB * NT / 32;        // 4736 warps
constexpr int NTILE = N0 / 32;          // 625 transpose tiles

// ---- scratch (device globals; zero-initialized at module load) ----
__device__ __half g_xT[N0 * Bb];
__device__ int    g_cnt[MTOT];          // re-zeroed by scan phase each call
__device__ int    g_slot[ETOT];
__device__ int    g_rp0[M0 + 1], g_rp1[M1 + 1], g_rp2[M2 + 1];
__device__ int    g_ce0[E0], g_ce1[E1], g_ce2[E2];
__device__ __half g_d1[M0 * Bb * 8];
__device__ __half g_d2[M1 * Bb * 8];
__device__ float  g_d3[M2 * Bb * 8];

// ---- software grid barrier (all NB CTAs resident by construction) ----
__device__ int           g_bcnt;
__device__ volatile int  g_bgen;

__device__ __forceinline__ void grid_barrier() {
    __syncthreads();
    if (threadIdx.x == 0) {
        int gen = g_bgen;
        __threadfence();
        if (atomicAdd(&g_bcnt, 1) == NB - 1) {
            g_bcnt = 0;
            __threadfence();
            g_bgen = gen + 1;
        } else {
            while (g_bgen == gen) { }
        }
    }
    __syncthreads();
}

__global__ void __launch_bounds__(NT, 4)
k_all(const float* __restrict__ x,
      const int* __restrict__ e0s, const int* __restrict__ e0d,
      const int* __restrict__ e1s, const int* __restrict__ e1d,
      const int* __restrict__ e2s, const int* __restrict__ e2d,
      const float* __restrict__ W0, const float* __restrict__ W1,
      const float* __restrict__ W2, const float* __restrict__ Wout,
      const float* __restrict__ bout, float* __restrict__ out) {

    __shared__ float s_tile[64][33];
    __shared__ int   s_wtot[8];
    __shared__ float s_W[64];

    const int tid   = threadIdx.x;
    const int lane  = tid & 31;
    const int gwarp = (blockIdx.x * NT + tid) >> 5;

    // ================= Phase A: transpose x -> xT fp16  ||  histogram =================
    {
        int tx = tid & 31, ty = tid >> 5;                 // ty 0..7
        for (int t = blockIdx.x; t < NTILE; t += NB) {
            int nb = t * 32;
#pragma unroll
            for (int i = 0; i < 64; i += 8)
                s_tile[ty + i][tx] = x[(ty + i) * N0 + nb + tx];
            __syncthreads();
            int r = tid >> 3, q = tid & 7;                // r: node 0..31, q: batch octet
            __half2 h[4];
#pragma unroll
            for (int k = 0; k < 4; k++)
                h[k] = __floats2half2_rn(s_tile[q * 8 + 2 * k][r],
                                         s_tile[q * 8 + 2 * k + 1][r]);
            *(uint4*)&g_xT[(nb + r) * Bb + q * 8] = *(uint4*)h;
            __syncthreads();
        }
        // histogram: one int4 quad per thread (75000 quads <= 151552 threads)
        int i0 = (blockIdx.x * NT + tid) * 4;
        if (i0 < ETOT) {
            const int* dp; int* cnt; int off;
            if (i0 < E0)            { dp = e0d; cnt = g_cnt;           off = 0; }
            else if (i0 < E0 + E1)  { dp = e1d; cnt = g_cnt + M0;      off = E0; }
            else                    { dp = e2d; cnt = g_cnt + M0 + M1; off = E0 + E1; }
            int4 dd = *(const int4*)&dp[i0 - off];
            int s0 = atomicAdd(&cnt[dd.x], 1);
            int s1 = atomicAdd(&cnt[dd.y], 1);
            int s2 = atomicAdd(&cnt[dd.z], 1);
            int s3 = atomicAdd(&cnt[dd.w], 1);
            *(int4*)&g_slot[i0] = make_int4(s0, s1, s2, s3);
        }
    }
    grid_barrier();

    // ===== Phase B: exclusive scans (blocks 0..2), two-pass, zero counters ============
    if (blockIdx.x < 3) {
        const int L = blockIdx.x;
        int* cnt    = (L == 0) ? g_cnt : (L == 1) ? g_cnt + M0 : g_cnt + M0 + M1;
        int* rp     = (L == 0) ? g_rp0 : (L == 1) ? g_rp1      : g_rp2;
        const int m = (L == 0) ? M0    : (L == 1) ? M1         : M2;
        const int chunk = (m + NT - 1) / NT;
        int base = tid * chunk;
        int s = 0;
        for (int k = 0; k < chunk; k++)
            if (base + k < m) s += cnt[base + k];
        int wid = tid >> 5;
        int inc = s;
#pragma unroll
        for (int off = 1; off < 32; off <<= 1) {
            int n = __shfl_up_sync(0xffffffffu, inc, off);
            if (lane >= off) inc += n;
        }
        if (lane == 31) s_wtot[wid] = inc;
        __syncthreads();
        if (tid < 8) {
            int w = s_wtot[tid];
            int wi = w;
#pragma unroll
            for (int off = 1; off < 8; off <<= 1) {
                int n = __shfl_up_sync(0xffu, wi, off);
                if (tid >= off) wi += n;
            }
            s_wtot[tid] = wi - w;
        }
        __syncthreads();
        int run = s_wtot[wid] + (inc - s);    // exclusive prefix for this thread
        for (int k = 0; k < chunk; k++) {
            int i = base + k;
            if (i < m) {
                run += cnt[i];
                rp[i + 1] = run;
                cnt[i] = 0;
            }
        }
        if (tid == 0) rp[0] = 0;
    }
    grid_barrier();

    // ================= Phase C: fill CSR (no atomics) =================================
    {
        int i0 = (blockIdx.x * NT + tid) * 4;
        if (i0 < ETOT) {
            const int *sp, *dp, *rp; int* ce; int off;
            if (i0 < E0)            { sp = e0s; dp = e0d; rp = g_rp0; ce = g_ce0; off = 0; }
            else if (i0 < E0 + E1)  { sp = e1s; dp = e1d; rp = g_rp1; ce = g_ce1; off = E0; }
            else                    { sp = e2s; dp = e2d; rp = g_rp2; ce = g_ce2; off = E0 + E1; }
            int j = i0 - off;
            int4 ss = *(const int4*)&sp[j];
            int4 dd = *(const int4*)&dp[j];
            int4 sl = *(const int4*)&g_slot[i0];
            ce[rp[dd.x] + sl.x] = ss.x;
            ce[rp[dd.y] + sl.y] = ss.y;
            ce[rp[dd.z] + sl.z] = ss.z;
            ce[rp[dd.w] + sl.w] = ss.w;
        }
    }
    grid_barrier();

    // ================= Phase D: layer 0 (warp per node, lane = 2 batches) =============
    {
        float w0r[8];
#pragma unroll
        for (int h = 0; h < 8; h++) w0r[h] = W0[h];
        for (int node = gwarp; node < M0; node += NW) {
            int beg = g_rp0[node], end = g_rp0[node + 1];
            float ax = 0.f, ay = 0.f;
            for (int c = beg; c < end; c += 32) {
                int nchunk = min(32, end - c);
                int idx = (c + lane < end) ? g_ce0[c + lane] : 0;
#pragma unroll 4
                for (int k = 0; k < nchunk; k++) {
                    int src = __shfl_sync(0xffffffffu, idx, k);
                    float2 f = __half22float2(*(const __half2*)&g_xT[src * Bb + 2 * lane]);
                    ax += f.x; ay += f.y;
                }
            }
            float inv = 1.f / fmaxf((float)(end - beg), 1.f);
            float s0 = ax * inv, s1 = ay * inv;
            float mn = fminf(s0, s1), mx = fmaxf(s0, s1);
#pragma unroll
            for (int off = 16; off; off >>= 1) {
                mn = fminf(mn, __shfl_xor_sync(0xffffffffu, mn, off));
                mx = fmaxf(mx, __shfl_xor_sync(0xffffffffu, mx, off));
            }
            __half2 o0[4], o1[4];
#pragma unroll
            for (int h = 0; h < 4; h++) {
                float wa = w0r[2 * h], wb = w0r[2 * h + 1];
                float loa = (wa >= 0.f) ? wa * mn : wa * mx;
                float hia = (wa >= 0.f) ? wa * mx : wa * mn;
                float lob = (wb >= 0.f) ? wb * mn : wb * mx;
                float hib = (wb >= 0.f) ? wb * mx : wb * mn;
                float ia = 1.f / (hia - loa + EPSV), ib = 1.f / (hib - lob + EPSV);
                o0[h] = __floats2half2_rn(fmaxf((wa * s0 - loa) * ia, 0.f),
                                          fmaxf((wb * s0 - lob) * ib, 0.f));
                o1[h] = __floats2half2_rn(fmaxf((wa * s1 - loa) * ia, 0.f),
                                          fmaxf((wb * s1 - lob) * ib, 0.f));
            }
            *(uint4*)&g_d1[(node * Bb + 2 * lane) * 8]     = *(uint4*)o0;
            *(uint4*)&g_d1[(node * Bb + 2 * lane + 1) * 8] = *(uint4*)o1;
        }
    }
    grid_barrier();

    // ================= Phases E/F: layers 1 and 2 =====================================
#pragma unroll 1
    for (int L = 1; L <= 2; L++) {
        const int*    rp  = (L == 1) ? g_rp1 : g_rp2;
        const int*    ce  = (L == 1) ? g_ce1 : g_ce2;
        const __half* din = (L == 1) ? g_d1  : g_d2;
        const float*  W   = (L == 1) ? W1    : W2;
        const int     m   = (L == 1) ? M1    : M2;
        if (tid < 64) s_W[tid] = W[tid];
        __syncthreads();
        for (int node = gwarp; node < m; node += NW) {
            int beg = rp[node], end = rp[node + 1];
            float a0[8], a1[8];
#pragma unroll
            for (int h = 0; h < 8; h++) { a0[h] = 0.f; a1[h] = 0.f; }
            for (int c = beg; c < end; c += 32) {
                int nchunk = min(32, end - c);
                int idx = (c + lane < end) ? ce[c + lane] : 0;
#pragma unroll 2
                for (int k = 0; k < nchunk; k++) {
                    int src = __shfl_sync(0xffffffffu, idx, k);
                    const uint4* p = (const uint4*)&din[(src * Bb + 2 * lane) * 8];
                    uint4 r0 = p[0], r1 = p[1];
                    float2 f;
                    f = __half22float2(*(__half2*)&r0.x); a0[0] += f.x; a0[1] += f.y;
                    f = __half22float2(*(__half2*)&r0.y); a0[2] += f.x; a0[3] += f.y;
                    f = __half22float2(*(__half2*)&r0.z); a0[4] += f.x; a0[5] += f.y;
                    f = __half22float2(*(__half2*)&r0.w); a0[6] += f.x; a0[7] += f.y;
                    f = __half22float2(*(__half2*)&r1.x); a1[0] += f.x; a1[1] += f.y;
                    f = __half22float2(*(__half2*)&r1.y); a1[2] += f.x; a1[3] += f.y;
                    f = __half22float2(*(__half2*)&r1.z); a1[4] += f.x; a1[5] += f.y;
                    f = __half22float2(*(__half2*)&r1.w); a1[6] += f.x; a1[7] += f.y;
                }
            }
            float inv = 1.f / fmaxf((float)(end - beg), 1.f);
            float t0[8], t1[8], mn[8], mx[8];
#pragma unroll
            for (int h = 0; h < 8; h++) {
                float v0 = 0.f, v1 = 0.f;
#pragma unroll
                for (int d = 0; d < 8; d++) {
                    float w = s_W[h * 8 + d];
                    v0 += w * a0[d]; v1 += w * a1[d];
                }
                t0[h] = v0 * inv; t1[h] = v1 * inv;
                mn[h] = fminf(t0[h], t1[h]); mx[h] = fmaxf(t0[h], t1[h]);
            }
#pragma unroll
            for (int off = 16; off; off >>= 1) {
#pragma unroll
                for (int h = 0; h < 8; h++) {
                    mn[h] = fminf(mn[h], __shfl_xor_sync(0xffffffffu, mn[h], off));
                    mx[h] = fmaxf(mx[h], __shfl_xor_sync(0xffffffffu, mx[h], off));
                }
            }
            if (L == 1) {
                __half2 p0[4], p1[4];
#pragma unroll
                for (int h = 0; h < 4; h++) {
                    float ia = 1.f / (mx[2 * h] - mn[2 * h] + EPSV);
                    float ib = 1.f / (mx[2 * h + 1] - mn[2 * h + 1] + EPSV);
                    p0[h] = __floats2half2_rn(fmaxf((t0[2 * h] - mn[2 * h]) * ia, 0.f),
                                              fmaxf((t0[2 * h + 1] - mn[2 * h + 1]) * ib, 0.f));
                    p1[h] = __floats2half2_rn(fmaxf((t1[2 * h] - mn[2 * h]) * ia, 0.f),
                                              fmaxf((t1[2 * h + 1] - mn[2 * h + 1]) * ib, 0.f));
                }
                *(uint4*)&g_d2[(node * Bb + 2 * lane) * 8]     = *(uint4*)p0;
                *(uint4*)&g_d2[(node * Bb + 2 * lane + 1) * 8] = *(uint4*)p1;
            } else {
                float o0[8], o1[8];
#pragma unroll
                for (int h = 0; h < 8; h++) {
                    float iv = 1.f / (mx[h] - mn[h] + EPSV);
                    o0[h] = fmaxf((t0[h] - mn[h]) * iv, 0.f);
                    o1[h] = fmaxf((t1[h] - mn[h]) * iv, 0.f);
                }
                float4* q = (float4*)&g_d3[(node * Bb + 2 * lane) * 8];
                q[0] = make_float4(o0[0], o0[1], o0[2], o0[3]);
                q[1] = make_float4(o0[4], o0[5], o0[6], o0[7]);
                q[2] = make_float4(o1[0], o1[1], o1[2], o1[3]);
                q[3] = make_float4(o1[4], o1[5], o1[6], o1[7]);
            }
        }
        grid_barrier();
    }

    // ================= Phase G: output dot (warp per batch) ===========================
    if (gwarp < Bb) {
        int b = gwarp;
        float p = 0.f;
        for (int i = lane; i < M2 * 8; i += 32)
            p += g_d3[((i >> 3) * Bb + b) * 8 + (i & 7)] * Wout[i];
#pragma unroll
        for (int off = 16; off; off >>= 1)
            p += __shfl_xor_sync(0xffffffffu, p, off);
        if (lane == 0) out[b] = p + bout[0];
    }
}

extern "C" void kernel_launch(void* const* d_in, const int* in_sizes, int n_in,
                              void* d_out, int out_size) {
    const float* x    = (const float*)d_in[0];
    const int*   e0s  = (const int*)d_in[1];
    const int*   e0d  = (const int*)d_in[2];
    const int*   e1s  = (const int*)d_in[3];
    const int*   e1d  = (const int*)d_in[4];
    const int*   e2s  = (const int*)d_in[5];
    const int*   e2d  = (const int*)d_in[6];
    const float* W0   = (const float*)d_in[7];
    const float* W1   = (const float*)d_in[8];
    const float* W2   = (const float*)d_in[9];
    const float* Wout = (const float*)d_in[10];
    const float* bout = (const float*)d_in[11];
    float* out = (float*)d_out;

    k_all<<<NB, NT>>>(x, e0s, e0d, e1s, e1d, e2s, e2d,
                      W0, W1, W2, Wout, bout, out);
}

// round 7
// speedup vs baseline: 1.0606x; 1.0606x over previous
#include <cuda_runtime.h>
#include <cuda_fp16.h>

#define EPSV 1e-8f

constexpr int Bb = 64;
constexpr int N0 = 20000, E0 = 200000, M0 = 8000;
constexpr int E1 = 80000,  M1 = 2000;
constexpr int E2 = 20000,  M2 = 500;
constexpr int ETOT = E0 + E1 + E2;
constexpr int MTOT = M0 + M1 + M2;

constexpr int NB = 740;                 // 5 CTAs/SM x 148 SMs -> wave-1 resident
constexpr int NT = 256;
constexpr int NWARP = NB * (NT / 32);   // 5920 warps
constexpr int NGROUP = NB * 4;          // 2960 64-thread groups
constexpr int NTILE = N0 / 32;          // 625

// ---- scratch (device globals; zero-initialized at module load) ----
__device__ __half g_xT[N0 * Bb];
__device__ int    g_cnt[MTOT];          // re-zeroed by scan phase each call
__device__ int    g_slot[ETOT];
__device__ int    g_rp0[M0 + 1], g_rp1[M1 + 1], g_rp2[M2 + 1];
__device__ int    g_ce0[E0], g_ce1[E1], g_ce2[E2];
__device__ __half g_d1[M0 * Bb * 8];
__device__ __half g_d2[M1 * Bb * 8];
__device__ float  g_d3[M2 * Bb * 8];

// ---- software grid barrier (all NB CTAs resident by construction) ----
__device__ int           g_bcnt;
__device__ volatile int  g_bgen;

__device__ __forceinline__ void grid_barrier() {
    __syncthreads();
    if (threadIdx.x == 0) {
        int gen = g_bgen;
        __threadfence();
        if (atomicAdd(&g_bcnt, 1) == NB - 1) {
            g_bcnt = 0;
            __threadfence();
            g_bgen = gen + 1;
        } else {
            while (g_bgen == gen) __nanosleep(64);
        }
    }
    __syncthreads();
}

__global__ void __launch_bounds__(NT, 5)
k_all(const float* __restrict__ x,
      const int* __restrict__ e0s, const int* __restrict__ e0d,
      const int* __restrict__ e1s, const int* __restrict__ e1d,
      const int* __restrict__ e2s, const int* __restrict__ e2d,
      const float* __restrict__ W0, const float* __restrict__ W1,
      const float* __restrict__ W2, const float* __restrict__ Wout,
      const float* __restrict__ bout, float* __restrict__ out) {

    __shared__ float s_tile[64][33];
    __shared__ int   s_wtot[8];
    __shared__ float s_W[64];
    __shared__ float s_mn[4][2][8], s_mx[4][2][8];

    const int tid  = threadIdx.x;
    const int lane = tid & 31;

    // ================= Phase A: transpose x -> xT fp16  ||  histogram =================
    {
        if (blockIdx.x < NTILE) {
            int tx = tid & 31, ty = tid >> 5;             // ty 0..7
            int nb = blockIdx.x * 32;
#pragma unroll
            for (int i = 0; i < 64; i += 8)
                s_tile[ty + i][tx] = x[(ty + i) * N0 + nb + tx];
            __syncthreads();
            int r = tid >> 3, q = tid & 7;
            __half2 h[4];
#pragma unroll
            for (int k = 0; k < 4; k++)
                h[k] = __floats2half2_rn(s_tile[q * 8 + 2 * k][r],
                                         s_tile[q * 8 + 2 * k + 1][r]);
            *(uint4*)&g_xT[(nb + r) * Bb + q * 8] = *(uint4*)h;
        }
        int i0 = (blockIdx.x * NT + tid) * 4;
        if (i0 < ETOT) {
            const int* dp; int* cnt; int off;
            if (i0 < E0)            { dp = e0d; cnt = g_cnt;           off = 0; }
            else if (i0 < E0 + E1)  { dp = e1d; cnt = g_cnt + M0;      off = E0; }
            else                    { dp = e2d; cnt = g_cnt + M0 + M1; off = E0 + E1; }
            int4 dd = *(const int4*)&dp[i0 - off];
            int s0 = atomicAdd(&cnt[dd.x], 1);
            int s1 = atomicAdd(&cnt[dd.y], 1);
            int s2 = atomicAdd(&cnt[dd.z], 1);
            int s3 = atomicAdd(&cnt[dd.w], 1);
            *(int4*)&g_slot[i0] = make_int4(s0, s1, s2, s3);
        }
    }
    grid_barrier();

    // ===== Phase B: exclusive scans (blocks 0..2), two-pass, zero counters ============
    if (blockIdx.x < 3) {
        const int L = blockIdx.x;
        int* cnt    = (L == 0) ? g_cnt : (L == 1) ? g_cnt + M0 : g_cnt + M0 + M1;
        int* rp     = (L == 0) ? g_rp0 : (L == 1) ? g_rp1      : g_rp2;
        const int m = (L == 0) ? M0    : (L == 1) ? M1         : M2;
        const int chunk = (m + NT - 1) / NT;
        int base = tid * chunk;
        int s = 0;
#pragma unroll 4
        for (int k = 0; k < chunk; k++)
            if (base + k < m) s += cnt[base + k];
        int wid = tid >> 5;
        int inc = s;
#pragma unroll
        for (int off = 1; off < 32; off <<= 1) {
            int n = __shfl_up_sync(0xffffffffu, inc, off);
            if (lane >= off) inc += n;
        }
        if (lane == 31) s_wtot[wid] = inc;
        __syncthreads();
        if (tid < 8) {
            int w = s_wtot[tid];
            int wi = w;
#pragma unroll
            for (int off = 1; off < 8; off <<= 1) {
                int n = __shfl_up_sync(0xffu, wi, off);
                if (tid >= off) wi += n;
            }
            s_wtot[tid] = wi - w;
        }
        __syncthreads();
        int run = s_wtot[wid] + (inc - s);
        for (int k = 0; k < chunk; k++) {
            int i = base + k;
            if (i < m) { run += cnt[i]; rp[i + 1] = run; cnt[i] = 0; }
        }
        if (tid == 0) rp[0] = 0;
    }
    grid_barrier();

    // ================= Phase C: fill CSR (no atomics) =================================
    {
        int i0 = (blockIdx.x * NT + tid) * 4;
        if (i0 < ETOT) {
            const int *sp, *dp, *rp; int* ce; int off;
            if (i0 < E0)            { sp = e0s; dp = e0d; rp = g_rp0; ce = g_ce0; off = 0; }
            else if (i0 < E0 + E1)  { sp = e1s; dp = e1d; rp = g_rp1; ce = g_ce1; off = E0; }
            else                    { sp = e2s; dp = e2d; rp = g_rp2; ce = g_ce2; off = E0 + E1; }
            int j = i0 - off;
            int4 ss = *(const int4*)&sp[j];
            int4 dd = *(const int4*)&dp[j];
            int4 sl = *(const int4*)&g_slot[i0];
            ce[rp[dd.x] + sl.x] = ss.x;
            ce[rp[dd.y] + sl.y] = ss.y;
            ce[rp[dd.z] + sl.z] = ss.z;
            ce[rp[dd.w] + sl.w] = ss.w;
        }
    }
    grid_barrier();

    // ===== Phase D: layer 0 — warp per node, lane = 2 batches (31-reg form) ===========
    {
        int gw = blockIdx.x * 8 + (tid >> 5);
        for (int node = gw; node < M0; node += NWARP) {
            int beg = g_rp0[node], end = g_rp0[node + 1];
            float ax = 0.f, ay = 0.f;
            for (int c = beg; c < end; c += 32) {
                int nchunk = min(32, end - c);
                int idx = (c + lane < end) ? g_ce0[c + lane] : 0;
#pragma unroll 4
                for (int k = 0; k < nchunk; k++) {
                    int src = __shfl_sync(0xffffffffu, idx, k);
                    float2 f = __half22float2(*(const __half2*)&g_xT[src * Bb + 2 * lane]);
                    ax += f.x; ay += f.y;
                }
            }
            float inv = 1.f / fmaxf((float)(end - beg), 1.f);
            float v0 = ax * inv, v1 = ay * inv;
            float mn = fminf(v0, v1), mx = fmaxf(v0, v1);
#pragma unroll
            for (int off = 16; off; off >>= 1) {
                mn = fminf(mn, __shfl_xor_sync(0xffffffffu, mn, off));
                mx = fmaxf(mx, __shfl_xor_sync(0xffffffffu, mx, off));
            }
            __half2 o0[4], o1[4];
#pragma unroll
            for (int h = 0; h < 4; h++) {
                float wa = W0[2 * h], wb = W0[2 * h + 1];
                float loa = (wa >= 0.f) ? wa * mn : wa * mx;
                float hia = (wa >= 0.f) ? wa * mx : wa * mn;
                float lob = (wb >= 0.f) ? wb * mn : wb * mx;
                float hib = (wb >= 0.f) ? wb * mx : wb * mn;
                float ia = 1.f / (hia - loa + EPSV), ib = 1.f / (hib - lob + EPSV);
                o0[h] = __floats2half2_rn(fmaxf((wa * v0 - loa) * ia, 0.f),
                                          fmaxf((wb * v0 - lob) * ib, 0.f));
                o1[h] = __floats2half2_rn(fmaxf((wa * v1 - loa) * ia, 0.f),
                                          fmaxf((wb * v1 - lob) * ib, 0.f));
            }
            *(uint4*)&g_d1[(node * Bb + 2 * lane) * 8]     = *(uint4*)o0;
            *(uint4*)&g_d1[(node * Bb + 2 * lane + 1) * 8] = *(uint4*)o1;
        }
    }
    grid_barrier();

    // ===== Phases E/F: layers 1/2 — 64-thread group per node, thread = 1 batch ========
    // M1=2000, M2=500 with 4 groups/CTA: active CTA sets are block-aligned, so all
    // __syncthreads below are CTA-uniform.
#pragma unroll 1
    for (int L = 1; L <= 2; L++) {
        const int*    rp  = (L == 1) ? g_rp1 : g_rp2;
        const int*    ce  = (L == 1) ? g_ce1 : g_ce2;
        const __half* din = (L == 1) ? g_d1  : g_d2;
        const float*  W   = (L == 1) ? W1    : W2;
        const int     m   = (L == 1) ? M1    : M2;
        if (tid < 64) s_W[tid] = W[tid];
        __syncthreads();
        const int group = tid >> 6;        // 0..3
        const int b     = tid & 63;
        const int node  = blockIdx.x * 4 + group;
        float t[8];
        if (node < m) {
            int beg = rp[node], end = rp[node + 1];
            float acc[8];
#pragma unroll
            for (int h = 0; h < 8; h++) acc[h] = 0.f;
            int j = beg;
            for (; j + 2 <= end; j += 2) {
                int iA = ce[j], iB = ce[j + 1];
                uint4 rA = *(const uint4*)&din[(iA * Bb + b) * 8];
                uint4 rB = *(const uint4*)&din[(iB * Bb + b) * 8];
                float2 f;
                f = __half22float2(*(__half2*)&rA.x); acc[0] += f.x; acc[1] += f.y;
                f = __half22float2(*(__half2*)&rA.y); acc[2] += f.x; acc[3] += f.y;
                f = __half22float2(*(__half2*)&rA.z); acc[4] += f.x; acc[5] += f.y;
                f = __half22float2(*(__half2*)&rA.w); acc[6] += f.x; acc[7] += f.y;
                f = __half22float2(*(__half2*)&rB.x); acc[0] += f.x; acc[1] += f.y;
                f = __half22float2(*(__half2*)&rB.y); acc[2] += f.x; acc[3] += f.y;
                f = __half22float2(*(__half2*)&rB.z); acc[4] += f.x; acc[5] += f.y;
                f = __half22float2(*(__half2*)&rB.w); acc[6] += f.x; acc[7] += f.y;
            }
            if (j < end) {
                int iA = ce[j];
                uint4 rA = *(const uint4*)&din[(iA * Bb + b) * 8];
                float2 f;
                f = __half22float2(*(__half2*)&rA.x); acc[0] += f.x; acc[1] += f.y;
                f = __half22float2(*(__half2*)&rA.y); acc[2] += f.x; acc[3] += f.y;
                f = __half22float2(*(__half2*)&rA.z); acc[4] += f.x; acc[5] += f.y;
                f = __half22float2(*(__half2*)&rA.w); acc[6] += f.x; acc[7] += f.y;
            }
            float inv = 1.f / fmaxf((float)(end - beg), 1.f);
#pragma unroll
            for (int h = 0; h < 8; h++) {
                float v = 0.f;
#pragma unroll
                for (int d = 0; d < 8; d++) v += s_W[h * 8 + d] * acc[d];
                t[h] = v * inv;
            }
            float mn[8], mx[8];
#pragma unroll
            for (int h = 0; h < 8; h++) { mn[h] = t[h]; mx[h] = t[h]; }
#pragma unroll
            for (int off = 16; off; off >>= 1) {
#pragma unroll
                for (int h = 0; h < 8; h++) {
                    mn[h] = fminf(mn[h], __shfl_xor_sync(0xffffffffu, mn[h], off));
                    mx[h] = fmaxf(mx[h], __shfl_xor_sync(0xffffffffu, mx[h], off));
                }
            }
            if (lane == 0) {
                int wig = (tid >> 5) & 1;
#pragma unroll
                for (int h = 0; h < 8; h++) {
                    s_mn[group][wig][h] = mn[h];
                    s_mx[group][wig][h] = mx[h];
                }
            }
        }
        __syncthreads();
        if (node < m) {
            if (L == 1) {
                __half2 p[4];
#pragma unroll
                for (int h = 0; h < 4; h++) {
                    float lo0 = fminf(s_mn[group][0][2 * h],     s_mn[group][1][2 * h]);
                    float hi0 = fmaxf(s_mx[group][0][2 * h],     s_mx[group][1][2 * h]);
                    float lo1 = fminf(s_mn[group][0][2 * h + 1], s_mn[group][1][2 * h + 1]);
                    float hi1 = fmaxf(s_mx[group][0][2 * h + 1], s_mx[group][1][2 * h + 1]);
                    p[h] = __floats2half2_rn(
                        fmaxf((t[2 * h]     - lo0) / (hi0 - lo0 + EPSV), 0.f),
                        fmaxf((t[2 * h + 1] - lo1) / (hi1 - lo1 + EPSV), 0.f));
                }
                *(uint4*)&g_d2[(node * Bb + b) * 8] = *(uint4*)p;
            } else {
                float o[8];
#pragma unroll
                for (int h = 0; h < 8; h++) {
                    float lo = fminf(s_mn[group][0][h], s_mn[group][1][h]);
                    float hi = fmaxf(s_mx[group][0][h], s_mx[group][1][h]);
                    o[h] = fmaxf((t[h] - lo) / (hi - lo + EPSV), 0.f);
                }
                float4* q = (float4*)&g_d3[(node * Bb + b) * 8];
                q[0] = make_float4(o[0], o[1], o[2], o[3]);
                q[1] = make_float4(o[4], o[5], o[6], o[7]);
            }
        }
        grid_barrier();
    }

    // ================= Phase G: output dot (warp per batch) ===========================
    {
        int gw = blockIdx.x * 8 + (tid >> 5);
        if (gw < Bb) {
            int b = gw;
            float p = 0.f;
            for (int i = lane; i < M2 * 8; i += 32)
                p += g_d3[((i >> 3) * Bb + b) * 8 + (i & 7)] * Wout[i];
#pragma unroll
            for (int off = 16; off; off >>= 1)
                p += __shfl_xor_sync(0xffffffffu, p, off);
            if (lane == 0) out[b] = p + bout[0];
        }
    }
}

extern "C" void kernel_launch(void* const* d_in, const int* in_sizes, int n_in,
                              void* d_out, int out_size) {
    const float* x    = (const float*)d_in[0];
    const int*   e0s  = (const int*)d_in[1];
    const int*   e0d  = (const int*)d_in[2];
    const int*   e1s  = (const int*)d_in[3];
    const int*   e1d  = (const int*)d_in[4];
    const int*   e2s  = (const int*)d_in[5];
    const int*   e2d  = (const int*)d_in[6];
    const float* W0   = (const float*)d_in[7];
    const float* W1   = (const float*)d_in[8];
    const float* W2   = (const float*)d_in[9];
    const float* Wout = (const float*)d_in[10];
    const float* bout = (const float*)d_in[11];
    float* out = (float*)d_out;

    k_all<<<NB, NT>>>(x, e0s, e0d, e1s, e1d, e2s, e2d,
                      W0, W1, W2, Wout, bout, out);
}

// round 8
// speedup vs baseline: 1.2373x; 1.1665x over previous
#include <cuda_runtime.h>
#include <cuda_fp16.h>

#define EPSV 1e-8f

constexpr int Bb = 64;
constexpr int N0 = 20000, E0 = 200000, M0 = 8000;
constexpr int E1 = 80000,  M1 = 2000;
constexpr int E2 = 20000,  M2 = 500;
constexpr int ETOT = E0 + E1 + E2;
constexpr int MTOT = M0 + M1 + M2;

constexpr int NB1 = 592;                // K1: 4 CTAs/SM x 148 SMs, wave-1 resident
constexpr int NT1 = 256;
constexpr int NTILE = N0 / 32;          // 625

// ---- scratch (device globals; zero-initialized at module load) ----
__device__ __half g_xT[N0 * Bb];
__device__ int    g_cnt[MTOT];          // re-zeroed by scan each call
__device__ int    g_slot[ETOT];
__device__ int    g_rp0[M0 + 1], g_rp1[M1 + 1], g_rp2[M2 + 1];
__device__ int    g_ce0[E0], g_ce1[E1], g_ce2[E2];
__device__ __half g_d1[M0 * Bb * 8];
__device__ __half g_d2[M1 * Bb * 8];

// ---- software grid barrier for K1 (all NB1 CTAs resident by construction) ----
__device__ int           g_bcnt;
__device__ volatile int  g_bgen;

__device__ __forceinline__ void grid_barrier() {
    __syncthreads();
    if (threadIdx.x == 0) {
        int gen = g_bgen;
        __threadfence();
        if (atomicAdd(&g_bcnt, 1) == NB1 - 1) {
            g_bcnt = 0;
            __threadfence();
            g_bgen = gen + 1;
        } else {
            while (g_bgen == gen) __nanosleep(32);
        }
    }
    __syncthreads();
}

// ================= K1: transpose+hist -> scan -> fill (mini-persistent) =============
__global__ void __launch_bounds__(NT1, 4)
k_build(const float* __restrict__ x,
        const int* __restrict__ e0s, const int* __restrict__ e0d,
        const int* __restrict__ e1s, const int* __restrict__ e1d,
        const int* __restrict__ e2s, const int* __restrict__ e2d,
        const float* __restrict__ bout, float* __restrict__ out) {

    __shared__ float s_tile[64][33];
    __shared__ int   s_wtot[8];

    const int tid  = threadIdx.x;
    const int lane = tid & 31;

    // ---- Phase A: out init || transpose (grid-stride tiles) || histogram ----
    if (blockIdx.x == 0 && tid < Bb) out[tid] = bout[0];
    {
        int tx = tid & 31, ty = tid >> 5;
        for (int t = blockIdx.x; t < NTILE; t += NB1) {
            int nb = t * 32;
#pragma unroll
            for (int i = 0; i < 64; i += 8)
                s_tile[ty + i][tx] = x[(ty + i) * N0 + nb + tx];
            __syncthreads();
            int r = tid >> 3, q = tid & 7;
            __half2 h[4];
#pragma unroll
            for (int k = 0; k < 4; k++)
                h[k] = __floats2half2_rn(s_tile[q * 8 + 2 * k][r],
                                         s_tile[q * 8 + 2 * k + 1][r]);
            *(uint4*)&g_xT[(nb + r) * Bb + q * 8] = *(uint4*)h;
            __syncthreads();
        }
        int i0 = (blockIdx.x * NT1 + tid) * 4;
        if (i0 < ETOT) {
            const int* dp; int* cnt; int off;
            if (i0 < E0)            { dp = e0d; cnt = g_cnt;           off = 0; }
            else if (i0 < E0 + E1)  { dp = e1d; cnt = g_cnt + M0;      off = E0; }
            else                    { dp = e2d; cnt = g_cnt + M0 + M1; off = E0 + E1; }
            int4 dd = *(const int4*)&dp[i0 - off];
            int s0 = atomicAdd(&cnt[dd.x], 1);
            int s1 = atomicAdd(&cnt[dd.y], 1);
            int s2 = atomicAdd(&cnt[dd.z], 1);
            int s3 = atomicAdd(&cnt[dd.w], 1);
            *(int4*)&g_slot[i0] = make_int4(s0, s1, s2, s3);
        }
    }
    grid_barrier();

    // ---- Phase B: exclusive scans (CTAs 0..2), two-pass, zero counters ----
    if (blockIdx.x < 3) {
        const int L = blockIdx.x;
        int* cnt    = (L == 0) ? g_cnt : (L == 1) ? g_cnt + M0 : g_cnt + M0 + M1;
        int* rp     = (L == 0) ? g_rp0 : (L == 1) ? g_rp1      : g_rp2;
        const int m = (L == 0) ? M0    : (L == 1) ? M1         : M2;
        const int chunk = (m + NT1 - 1) / NT1;
        int base = tid * chunk;
        int s = 0;
#pragma unroll 4
        for (int k = 0; k < chunk; k++)
            if (base + k < m) s += cnt[base + k];
        int wid = tid >> 5;
        int inc = s;
#pragma unroll
        for (int off = 1; off < 32; off <<= 1) {
            int n = __shfl_up_sync(0xffffffffu, inc, off);
            if (lane >= off) inc += n;
        }
        if (lane == 31) s_wtot[wid] = inc;
        __syncthreads();
        if (tid < 8) {
            int w = s_wtot[tid];
            int wi = w;
#pragma unroll
            for (int off = 1; off < 8; off <<= 1) {
                int n = __shfl_up_sync(0xffu, wi, off);
                if (tid >= off) wi += n;
            }
            s_wtot[tid] = wi - w;
        }
        __syncthreads();
        int run = s_wtot[wid] + (inc - s);
        for (int k = 0; k < chunk; k++) {
            int i = base + k;
            if (i < m) { run += cnt[i]; rp[i + 1] = run; cnt[i] = 0; }
        }
        if (tid == 0) rp[0] = 0;
    }
    grid_barrier();

    // ---- Phase C: fill CSR (no atomics) ----
    {
        int i0 = (blockIdx.x * NT1 + tid) * 4;
        if (i0 < ETOT) {
            const int *sp, *dp, *rp; int* ce; int off;
            if (i0 < E0)            { sp = e0s; dp = e0d; rp = g_rp0; ce = g_ce0; off = 0; }
            else if (i0 < E0 + E1)  { sp = e1s; dp = e1d; rp = g_rp1; ce = g_ce1; off = E0; }
            else                    { sp = e2s; dp = e2d; rp = g_rp2; ce = g_ce2; off = E0 + E1; }
            int j = i0 - off;
            int4 ss = *(const int4*)&sp[j];
            int4 dd = *(const int4*)&dp[j];
            int4 sl = *(const int4*)&g_slot[i0];
            ce[rp[dd.x] + sl.x] = ss.x;
            ce[rp[dd.y] + sl.y] = ss.y;
            ce[rp[dd.z] + sl.z] = ss.z;
            ce[rp[dd.w] + sl.w] = ss.w;
        }
    }
}

// ================= K2: layer 0 — warp per node, lane = 2 batches ====================
__global__ void k_agg0(const float* __restrict__ W0) {
    int lane = threadIdx.x & 31;
    int node = blockIdx.x * 8 + (threadIdx.x >> 5);
    int beg = g_rp0[node], end = g_rp0[node + 1];
    float ax = 0.f, ay = 0.f;
    for (int c = beg; c < end; c += 32) {
        int nchunk = min(32, end - c);
        int idx = (c + lane < end) ? g_ce0[c + lane] : 0;
        int k = 0;
#pragma unroll 2
        for (; k + 2 <= nchunk; k += 2) {
            int sA = __shfl_sync(0xffffffffu, idx, k);
            int sB = __shfl_sync(0xffffffffu, idx, k + 1);
            float2 fA = __half22float2(*(const __half2*)&g_xT[sA * Bb + 2 * lane]);
            float2 fB = __half22float2(*(const __half2*)&g_xT[sB * Bb + 2 * lane]);
            ax += fA.x + fB.x; ay += fA.y + fB.y;
        }
        if (k < nchunk) {
            int sA = __shfl_sync(0xffffffffu, idx, k);
            float2 fA = __half22float2(*(const __half2*)&g_xT[sA * Bb + 2 * lane]);
            ax += fA.x; ay += fA.y;
        }
    }
    float inv = 1.f / fmaxf((float)(end - beg), 1.f);
    float v0 = ax * inv, v1 = ay * inv;
    float mn = fminf(v0, v1), mx = fmaxf(v0, v1);
#pragma unroll
    for (int off = 16; off; off >>= 1) {
        mn = fminf(mn, __shfl_xor_sync(0xffffffffu, mn, off));
        mx = fmaxf(mx, __shfl_xor_sync(0xffffffffu, mx, off));
    }
    __half2 o0[4], o1[4];
#pragma unroll
    for (int h = 0; h < 4; h++) {
        float wa = W0[2 * h], wb = W0[2 * h + 1];
        float loa = (wa >= 0.f) ? wa * mn : wa * mx;
        float hia = (wa >= 0.f) ? wa * mx : wa * mn;
        float lob = (wb >= 0.f) ? wb * mn : wb * mx;
        float hib = (wb >= 0.f) ? wb * mx : wb * mn;
        float ia = 1.f / (hia - loa + EPSV), ib = 1.f / (hib - lob + EPSV);
        o0[h] = __floats2half2_rn(fmaxf((wa * v0 - loa) * ia, 0.f),
                                  fmaxf((wb * v0 - lob) * ib, 0.f));
        o1[h] = __floats2half2_rn(fmaxf((wa * v1 - loa) * ia, 0.f),
                                  fmaxf((wb * v1 - lob) * ib, 0.f));
    }
    *(uint4*)&g_d1[(node * Bb + 2 * lane) * 8]     = *(uint4*)o0;
    *(uint4*)&g_d1[(node * Bb + 2 * lane + 1) * 8] = *(uint4*)o1;
}

// ================= K3: layer 1 — warp per node, lane = 2 batches ====================
__global__ void k_agg1(const float* __restrict__ W1) {
    __shared__ float sW[64];
    if (threadIdx.x < 64) sW[threadIdx.x] = W1[threadIdx.x];
    __syncthreads();
    int lane = threadIdx.x & 31;
    int node = blockIdx.x * 8 + (threadIdx.x >> 5);
    int beg = g_rp1[node], end = g_rp1[node + 1];
    float a0[8], a1[8];
#pragma unroll
    for (int h = 0; h < 8; h++) { a0[h] = 0.f; a1[h] = 0.f; }
    for (int c = beg; c < end; c += 32) {
        int nchunk = min(32, end - c);
        int idx = (c + lane < end) ? g_ce1[c + lane] : 0;
#pragma unroll 2
        for (int k = 0; k < nchunk; k++) {
            int src = __shfl_sync(0xffffffffu, idx, k);
            const uint4* p = (const uint4*)&g_d1[(src * Bb + 2 * lane) * 8];
            uint4 r0 = p[0], r1 = p[1];
            float2 f;
            f = __half22float2(*(__half2*)&r0.x); a0[0] += f.x; a0[1] += f.y;
            f = __half22float2(*(__half2*)&r0.y); a0[2] += f.x; a0[3] += f.y;
            f = __half22float2(*(__half2*)&r0.z); a0[4] += f.x; a0[5] += f.y;
            f = __half22float2(*(__half2*)&r0.w); a0[6] += f.x; a0[7] += f.y;
            f = __half22float2(*(__half2*)&r1.x); a1[0] += f.x; a1[1] += f.y;
            f = __half22float2(*(__half2*)&r1.y); a1[2] += f.x; a1[3] += f.y;
            f = __half22float2(*(__half2*)&r1.z); a1[4] += f.x; a1[5] += f.y;
            f = __half22float2(*(__half2*)&r1.w); a1[6] += f.x; a1[7] += f.y;
        }
    }
    float inv = 1.f / fmaxf((float)(end - beg), 1.f);
    float t0[8], t1[8], mn[8], mx[8];
#pragma unroll
    for (int h = 0; h < 8; h++) {
        float v0 = 0.f, v1 = 0.f;
#pragma unroll
        for (int d = 0; d < 8; d++) {
            float w = sW[h * 8 + d];
            v0 += w * a0[d]; v1 += w * a1[d];
        }
        t0[h] = v0 * inv; t1[h] = v1 * inv;
        mn[h] = fminf(t0[h], t1[h]); mx[h] = fmaxf(t0[h], t1[h]);
    }
#pragma unroll
    for (int off = 16; off; off >>= 1) {
#pragma unroll
        for (int h = 0; h < 8; h++) {
            mn[h] = fminf(mn[h], __shfl_xor_sync(0xffffffffu, mn[h], off));
            mx[h] = fmaxf(mx[h], __shfl_xor_sync(0xffffffffu, mx[h], off));
        }
    }
    __half2 p0[4], p1[4];
#pragma unroll
    for (int h = 0; h < 4; h++) {
        float ia = 1.f / (mx[2 * h] - mn[2 * h] + EPSV);
        float ib = 1.f / (mx[2 * h + 1] - mn[2 * h + 1] + EPSV);
        p0[h] = __floats2half2_rn(fmaxf((t0[2 * h] - mn[2 * h]) * ia, 0.f),
                                  fmaxf((t0[2 * h + 1] - mn[2 * h + 1]) * ib, 0.f));
        p1[h] = __floats2half2_rn(fmaxf((t1[2 * h] - mn[2 * h]) * ia, 0.f),
                                  fmaxf((t1[2 * h + 1] - mn[2 * h + 1]) * ib, 0.f));
    }
    *(uint4*)&g_d2[(node * Bb + 2 * lane) * 8]     = *(uint4*)p0;
    *(uint4*)&g_d2[(node * Bb + 2 * lane + 1) * 8] = *(uint4*)p1;
}

// ======= K4: layer 2 + output dot, fused. 64-thread group per node, thread = batch ===
__global__ void k_agg2out(const float* __restrict__ W2, const float* __restrict__ Wout,
                          float* __restrict__ out) {
    __shared__ float s_W[64];
    __shared__ float s_mn[4][2][8], s_mx[4][2][8];
    __shared__ float s_part[Bb];
    const int tid = threadIdx.x;
    if (tid < 64) s_W[tid] = W2[tid];
    if (tid < Bb) s_part[tid] = 0.f;
    __syncthreads();
    const int group = tid >> 6;
    const int b     = tid & 63;
    const int lane  = tid & 31;
    const int node  = blockIdx.x * 4 + group;
    int beg = g_rp2[node], end = g_rp2[node + 1];
    float acc[8];
#pragma unroll
    for (int h = 0; h < 8; h++) acc[h] = 0.f;
    int j = beg;
    for (; j + 2 <= end; j += 2) {
        int iA = g_ce2[j], iB = g_ce2[j + 1];
        uint4 rA = *(const uint4*)&g_d2[(iA * Bb + b) * 8];
        uint4 rB = *(const uint4*)&g_d2[(iB * Bb + b) * 8];
        float2 f;
        f = __half22float2(*(__half2*)&rA.x); acc[0] += f.x; acc[1] += f.y;
        f = __half22float2(*(__half2*)&rA.y); acc[2] += f.x; acc[3] += f.y;
        f = __half22float2(*(__half2*)&rA.z); acc[4] += f.x; acc[5] += f.y;
        f = __half22float2(*(__half2*)&rA.w); acc[6] += f.x; acc[7] += f.y;
        f = __half22float2(*(__half2*)&rB.x); acc[0] += f.x; acc[1] += f.y;
        f = __half22float2(*(__half2*)&rB.y); acc[2] += f.x; acc[3] += f.y;
        f = __half22float2(*(__half2*)&rB.z); acc[4] += f.x; acc[5] += f.y;
        f = __half22float2(*(__half2*)&rB.w); acc[6] += f.x; acc[7] += f.y;
    }
    if (j < end) {
        int iA = g_ce2[j];
        uint4 rA = *(const uint4*)&g_d2[(iA * Bb + b) * 8];
        float2 f;
        f = __half22float2(*(__half2*)&rA.x); acc[0] += f.x; acc[1] += f.y;
        f = __half22float2(*(__half2*)&rA.y); acc[2] += f.x; acc[3] += f.y;
        f = __half22float2(*(__half2*)&rA.z); acc[4] += f.x; acc[5] += f.y;
        f = __half22float2(*(__half2*)&rA.w); acc[6] += f.x; acc[7] += f.y;
    }
    float inv = 1.f / fmaxf((float)(end - beg), 1.f);
    float t[8], mn[8], mx[8];
#pragma unroll
    for (int h = 0; h < 8; h++) {
        float v = 0.f;
#pragma unroll
        for (int d = 0; d < 8; d++) v += s_W[h * 8 + d] * acc[d];
        t[h] = v * inv;
        mn[h] = t[h]; mx[h] = t[h];
    }
#pragma unroll
    for (int off = 16; off; off >>= 1) {
#pragma unroll
        for (int h = 0; h < 8; h++) {
            mn[h] = fminf(mn[h], __shfl_xor_sync(0xffffffffu, mn[h], off));
            mx[h] = fmaxf(mx[h], __shfl_xor_sync(0xffffffffu, mx[h], off));
        }
    }
    if (lane == 0) {
        int wig = (tid >> 5) & 1;
#pragma unroll
        for (int h = 0; h < 8; h++) { s_mn[group][wig][h] = mn[h]; s_mx[group][wig][h] = mx[h]; }
    }
    __syncthreads();
    float p = 0.f;
#pragma unroll
    for (int h = 0; h < 8; h++) {
        float lo = fminf(s_mn[group][0][h], s_mn[group][1][h]);
        float hi = fmaxf(s_mx[group][0][h], s_mx[group][1][h]);
        float o = fmaxf((t[h] - lo) / (hi - lo + EPSV), 0.f);
        p += o * Wout[node * 8 + h];
    }
    atomicAdd(&s_part[b], p);
    __syncthreads();
    if (tid < Bb) atomicAdd(&out[tid], s_part[tid]);
}

extern "C" void kernel_launch(void* const* d_in, const int* in_sizes, int n_in,
                              void* d_out, int out_size) {
    const float* x    = (const float*)d_in[0];
    const int*   e0s  = (const int*)d_in[1];
    const int*   e0d  = (const int*)d_in[2];
    const int*   e1s  = (const int*)d_in[3];
    const int*   e1d  = (const int*)d_in[4];
    const int*   e2s  = (const int*)d_in[5];
    const int*   e2d  = (const int*)d_in[6];
    const float* W0   = (const float*)d_in[7];
    const float* W1   = (const float*)d_in[8];
    const float* W2   = (const float*)d_in[9];
    const float* Wout = (const float*)d_in[10];
    const float* bout = (const float*)d_in[11];
    float* out = (float*)d_out;

    k_build<<<NB1, NT1>>>(x, e0s, e0d, e1s, e1d, e2s, e2d, bout, out);
    k_agg0<<<M0 / 8, 256>>>(W0);
    k_agg1<<<M1 / 8, 256>>>(W1);
    k_agg2out<<<M2 / 4, 256>>>(W2, Wout, out);
}

// round 9
// speedup vs baseline: 1.3822x; 1.1171x over previous
#include <cuda_runtime.h>
#include <cuda_fp16.h>

#define EPSV 1e-8f

constexpr int Bb = 64;
constexpr int N0 = 20000, E0 = 200000, M0 = 8000;
constexpr int E1 = 80000,  M1 = 2000;
constexpr int E2 = 20000,  M2 = 500;
constexpr int ETOT = E0 + E1 + E2;
constexpr int MTOT = M0 + M1 + M2;

constexpr int NB1 = 592;                // K1: 4 CTAs/SM x 148 SMs, wave-1 resident
constexpr int NT1 = 256;
constexpr int NTILE = N0 / 32;          // 625

// ---- scratch (device globals; zero-initialized at module load) ----
__device__ __half g_xT[N0 * Bb];
__device__ int    g_cnt[MTOT];          // re-zeroed by scan each call
__device__ int    g_slot[ETOT];
__device__ int    g_rp0[M0 + 1], g_rp1[M1 + 1], g_rp2[M2 + 1];
__device__ int    g_ce0[E0], g_ce1[E1], g_ce2[E2];
__device__ __half g_d1[M0 * Bb * 8];
__device__ __half g_d2[M1 * Bb * 8];

// ---- software grid barrier for K1 (all NB1 CTAs resident by construction) ----
__device__ int           g_bcnt;
__device__ volatile int  g_bgen;

__device__ __forceinline__ void grid_barrier() {
    __syncthreads();
    if (threadIdx.x == 0) {
        int gen = g_bgen;
        __threadfence();
        if (atomicAdd(&g_bcnt, 1) == NB1 - 1) {
            g_bcnt = 0;
            __threadfence();
            g_bgen = gen + 1;
        } else {
            while (g_bgen == gen) __nanosleep(32);
        }
    }
    __syncthreads();
}

// ================= K1: transpose+hist -> scan -> fill (mini-persistent) =============
__global__ void __launch_bounds__(NT1, 4)
k_build(const float* __restrict__ x,
        const int* __restrict__ e0s, const int* __restrict__ e0d,
        const int* __restrict__ e1s, const int* __restrict__ e1d,
        const int* __restrict__ e2s, const int* __restrict__ e2d,
        const float* __restrict__ bout, float* __restrict__ out) {

    __shared__ float s_tile[64][33];
    __shared__ int   s_wtot[8];

    const int tid  = threadIdx.x;
    const int lane = tid & 31;

    // ---- Phase A: out init || transpose (grid-stride tiles) || histogram ----
    if (blockIdx.x == 0 && tid < Bb) out[tid] = bout[0];
    {
        int tx = tid & 31, ty = tid >> 5;
        for (int t = blockIdx.x; t < NTILE; t += NB1) {
            int nb = t * 32;
#pragma unroll
            for (int i = 0; i < 64; i += 8)
                s_tile[ty + i][tx] = x[(ty + i) * N0 + nb + tx];
            __syncthreads();
            int r = tid >> 3, q = tid & 7;
            __half2 h[4];
#pragma unroll
            for (int k = 0; k < 4; k++)
                h[k] = __floats2half2_rn(s_tile[q * 8 + 2 * k][r],
                                         s_tile[q * 8 + 2 * k + 1][r]);
            *(uint4*)&g_xT[(nb + r) * Bb + q * 8] = *(uint4*)h;
            __syncthreads();
        }
        int i0 = (blockIdx.x * NT1 + tid) * 4;
        if (i0 < ETOT) {
            const int* dp; int* cnt; int off;
            if (i0 < E0)            { dp = e0d; cnt = g_cnt;           off = 0; }
            else if (i0 < E0 + E1)  { dp = e1d; cnt = g_cnt + M0;      off = E0; }
            else                    { dp = e2d; cnt = g_cnt + M0 + M1; off = E0 + E1; }
            int4 dd = *(const int4*)&dp[i0 - off];
            int s0 = atomicAdd(&cnt[dd.x], 1);
            int s1 = atomicAdd(&cnt[dd.y], 1);
            int s2 = atomicAdd(&cnt[dd.z], 1);
            int s3 = atomicAdd(&cnt[dd.w], 1);
            *(int4*)&g_slot[i0] = make_int4(s0, s1, s2, s3);
        }
    }
    grid_barrier();

    // ---- Phase B: exclusive scans (CTAs 0..2), two-pass, zero counters ----
    if (blockIdx.x < 3) {
        const int L = blockIdx.x;
        int* cnt    = (L == 0) ? g_cnt : (L == 1) ? g_cnt + M0 : g_cnt + M0 + M1;
        int* rp     = (L == 0) ? g_rp0 : (L == 1) ? g_rp1      : g_rp2;
        const int m = (L == 0) ? M0    : (L == 1) ? M1         : M2;
        const int chunk = (m + NT1 - 1) / NT1;
        int base = tid * chunk;
        int s = 0;
#pragma unroll 4
        for (int k = 0; k < chunk; k++)
            if (base + k < m) s += cnt[base + k];
        int wid = tid >> 5;
        int inc = s;
#pragma unroll
        for (int off = 1; off < 32; off <<= 1) {
            int n = __shfl_up_sync(0xffffffffu, inc, off);
            if (lane >= off) inc += n;
        }
        if (lane == 31) s_wtot[wid] = inc;
        __syncthreads();
        if (tid < 8) {
            int w = s_wtot[tid];
            int wi = w;
#pragma unroll
            for (int off = 1; off < 8; off <<= 1) {
                int n = __shfl_up_sync(0xffu, wi, off);
                if (tid >= off) wi += n;
            }
            s_wtot[tid] = wi - w;
        }
        __syncthreads();
        int run = s_wtot[wid] + (inc - s);
        for (int k = 0; k < chunk; k++) {
            int i = base + k;
            if (i < m) { run += cnt[i]; rp[i + 1] = run; cnt[i] = 0; }
        }
        if (tid == 0) rp[0] = 0;
    }
    grid_barrier();

    // ---- Phase C: fill CSR (no atomics) ----
    {
        int i0 = (blockIdx.x * NT1 + tid) * 4;
        if (i0 < ETOT) {
            const int *sp, *dp, *rp; int* ce; int off;
            if (i0 < E0)            { sp = e0s; dp = e0d; rp = g_rp0; ce = g_ce0; off = 0; }
            else if (i0 < E0 + E1)  { sp = e1s; dp = e1d; rp = g_rp1; ce = g_ce1; off = E0; }
            else                    { sp = e2s; dp = e2d; rp = g_rp2; ce = g_ce2; off = E0 + E1; }
            int j = i0 - off;
            int4 ss = *(const int4*)&sp[j];
            int4 dd = *(const int4*)&dp[j];
            int4 sl = *(const int4*)&g_slot[i0];
            ce[rp[dd.x] + sl.x] = ss.x;
            ce[rp[dd.y] + sl.y] = ss.y;
            ce[rp[dd.z] + sl.z] = ss.z;
            ce[rp[dd.w] + sl.w] = ss.w;
        }
    }
}

// ================= K2: layer 0 — warp per node, lane = 2 batches ====================
__global__ void k_agg0(const float* __restrict__ W0) {
    int lane = threadIdx.x & 31;
    int node = blockIdx.x * 8 + (threadIdx.x >> 5);
    int beg = g_rp0[node], end = g_rp0[node + 1];
    float ax = 0.f, ay = 0.f;
    for (int c = beg; c < end; c += 32) {
        int nchunk = min(32, end - c);
        int idx = (c + lane < end) ? g_ce0[c + lane] : 0;
        int k = 0;
#pragma unroll 2
        for (; k + 2 <= nchunk; k += 2) {
            int sA = __shfl_sync(0xffffffffu, idx, k);
            int sB = __shfl_sync(0xffffffffu, idx, k + 1);
            float2 fA = __half22float2(*(const __half2*)&g_xT[sA * Bb + 2 * lane]);
            float2 fB = __half22float2(*(const __half2*)&g_xT[sB * Bb + 2 * lane]);
            ax += fA.x + fB.x; ay += fA.y + fB.y;
        }
        if (k < nchunk) {
            int sA = __shfl_sync(0xffffffffu, idx, k);
            float2 fA = __half22float2(*(const __half2*)&g_xT[sA * Bb + 2 * lane]);
            ax += fA.x; ay += fA.y;
        }
    }
    float inv = 1.f / fmaxf((float)(end - beg), 1.f);
    float v0 = ax * inv, v1 = ay * inv;
    float mn = fminf(v0, v1), mx = fmaxf(v0, v1);
#pragma unroll
    for (int off = 16; off; off >>= 1) {
        mn = fminf(mn, __shfl_xor_sync(0xffffffffu, mn, off));
        mx = fmaxf(mx, __shfl_xor_sync(0xffffffffu, mx, off));
    }
    __half2 o0[4], o1[4];
#pragma unroll
    for (int h = 0; h < 4; h++) {
        float wa = W0[2 * h], wb = W0[2 * h + 1];
        float loa = (wa >= 0.f) ? wa * mn : wa * mx;
        float hia = (wa >= 0.f) ? wa * mx : wa * mn;
        float lob = (wb >= 0.f) ? wb * mn : wb * mx;
        float hib = (wb >= 0.f) ? wb * mx : wb * mn;
        float ia = 1.f / (hia - loa + EPSV), ib = 1.f / (hib - lob + EPSV);
        o0[h] = __floats2half2_rn(fmaxf((wa * v0 - loa) * ia, 0.f),
                                  fmaxf((wb * v0 - lob) * ib, 0.f));
        o1[h] = __floats2half2_rn(fmaxf((wa * v1 - loa) * ia, 0.f),
                                  fmaxf((wb * v1 - lob) * ib, 0.f));
    }
    *(uint4*)&g_d1[(node * Bb + 2 * lane) * 8]     = *(uint4*)o0;
    *(uint4*)&g_d1[(node * Bb + 2 * lane + 1) * 8] = *(uint4*)o1;
}

// ====== K3: layer 1 — 64-thread group per node (thread = batch), 4 nodes/CTA ========
__global__ void k_agg1(const float* __restrict__ W1) {
    __shared__ float s_W[64];
    __shared__ float s_mn[4][2][8], s_mx[4][2][8];
    const int tid = threadIdx.x;
    if (tid < 64) s_W[tid] = W1[tid];
    __syncthreads();
    const int group = tid >> 6;
    const int b     = tid & 63;
    const int lane  = tid & 31;
    const int node  = blockIdx.x * 4 + group;
    int beg = g_rp1[node], end = g_rp1[node + 1];
    float acc[8];
#pragma unroll
    for (int h = 0; h < 8; h++) acc[h] = 0.f;
    int j = beg;
    for (; j + 2 <= end; j += 2) {
        int iA = g_ce1[j], iB = g_ce1[j + 1];
        uint4 rA = *(const uint4*)&g_d1[(iA * Bb + b) * 8];
        uint4 rB = *(const uint4*)&g_d1[(iB * Bb + b) * 8];
        float2 f;
        f = __half22float2(*(__half2*)&rA.x); acc[0] += f.x; acc[1] += f.y;
        f = __half22float2(*(__half2*)&rA.y); acc[2] += f.x; acc[3] += f.y;
        f = __half22float2(*(__half2*)&rA.z); acc[4] += f.x; acc[5] += f.y;
        f = __half22float2(*(__half2*)&rA.w); acc[6] += f.x; acc[7] += f.y;
        f = __half22float2(*(__half2*)&rB.x); acc[0] += f.x; acc[1] += f.y;
        f = __half22float2(*(__half2*)&rB.y); acc[2] += f.x; acc[3] += f.y;
        f = __half22float2(*(__half2*)&rB.z); acc[4] += f.x; acc[5] += f.y;
        f = __half22float2(*(__half2*)&rB.w); acc[6] += f.x; acc[7] += f.y;
    }
    if (j < end) {
        int iA = g_ce1[j];
        uint4 rA = *(const uint4*)&g_d1[(iA * Bb + b) * 8];
        float2 f;
        f = __half22float2(*(__half2*)&rA.x); acc[0] += f.x; acc[1] += f.y;
        f = __half22float2(*(__half2*)&rA.y); acc[2] += f.x; acc[3] += f.y;
        f = __half22float2(*(__half2*)&rA.z); acc[4] += f.x; acc[5] += f.y;
        f = __half22float2(*(__half2*)&rA.w); acc[6] += f.x; acc[7] += f.y;
    }
    float inv = 1.f / fmaxf((float)(end - beg), 1.f);
    float t[8], mn[8], mx[8];
#pragma unroll
    for (int h = 0; h < 8; h++) {
        float v = 0.f;
#pragma unroll
        for (int d = 0; d < 8; d++) v += s_W[h * 8 + d] * acc[d];
        t[h] = v * inv;
        mn[h] = t[h]; mx[h] = t[h];
    }
#pragma unroll
    for (int off = 16; off; off >>= 1) {
#pragma unroll
        for (int h = 0; h < 8; h++) {
            mn[h] = fminf(mn[h], __shfl_xor_sync(0xffffffffu, mn[h], off));
            mx[h] = fmaxf(mx[h], __shfl_xor_sync(0xffffffffu, mx[h], off));
        }
    }
    if (lane == 0) {
        int wig = (tid >> 5) & 1;
#pragma unroll
        for (int h = 0; h < 8; h++) { s_mn[group][wig][h] = mn[h]; s_mx[group][wig][h] = mx[h]; }
    }
    __syncthreads();
    __half2 p[4];
#pragma unroll
    for (int h = 0; h < 4; h++) {
        float lo0 = fminf(s_mn[group][0][2 * h],     s_mn[group][1][2 * h]);
        float hi0 = fmaxf(s_mx[group][0][2 * h],     s_mx[group][1][2 * h]);
        float lo1 = fminf(s_mn[group][0][2 * h + 1], s_mn[group][1][2 * h + 1]);
        float hi1 = fmaxf(s_mx[group][0][2 * h + 1], s_mx[group][1][2 * h + 1]);
        p[h] = __floats2half2_rn(fmaxf((t[2 * h]     - lo0) / (hi0 - lo0 + EPSV), 0.f),
                                 fmaxf((t[2 * h + 1] - lo1) / (hi1 - lo1 + EPSV), 0.f));
    }
    *(uint4*)&g_d2[(node * Bb + b) * 8] = *(uint4*)p;
}

// ======= K4: layer 2 + out. ONE node per 256-thr block: 4 edge-chunks x 64 batches ===
__global__ void k_agg2out(const float* __restrict__ W2, const float* __restrict__ Wout,
                          float* __restrict__ out) {
    __shared__ float s_W[64];
    __shared__ float s_acc[4][64][8];
    __shared__ float s_mn[2][8], s_mx[2][8];
    const int tid   = threadIdx.x;
    const int chunk = tid >> 6;          // 0..3
    const int b     = tid & 63;
    const int node  = blockIdx.x;
    if (tid < 64) s_W[tid] = W2[tid];
    __syncthreads();
    int beg = g_rp2[node], end = g_rp2[node + 1];
    float acc[8];
#pragma unroll
    for (int h = 0; h < 8; h++) acc[h] = 0.f;
    for (int j = beg + chunk; j < end; j += 4) {
        int src = g_ce2[j];
        uint4 r = *(const uint4*)&g_d2[(src * Bb + b) * 8];
        float2 f;
        f = __half22float2(*(__half2*)&r.x); acc[0] += f.x; acc[1] += f.y;
        f = __half22float2(*(__half2*)&r.y); acc[2] += f.x; acc[3] += f.y;
        f = __half22float2(*(__half2*)&r.z); acc[4] += f.x; acc[5] += f.y;
        f = __half22float2(*(__half2*)&r.w); acc[6] += f.x; acc[7] += f.y;
    }
#pragma unroll
    for (int h = 0; h < 8; h++) s_acc[chunk][b][h] = acc[h];
    __syncthreads();
    if (tid < 64) {
        const int lane = tid & 31;
        const int wig  = tid >> 5;
#pragma unroll
        for (int h = 0; h < 8; h++)
            acc[h] = s_acc[0][b][h] + s_acc[1][b][h] + s_acc[2][b][h] + s_acc[3][b][h];
        float inv = 1.f / fmaxf((float)(end - beg), 1.f);
        float t[8], mn[8], mx[8];
#pragma unroll
        for (int h = 0; h < 8; h++) {
            float v = 0.f;
#pragma unroll
            for (int d = 0; d < 8; d++) v += s_W[h * 8 + d] * acc[d];
            t[h] = v * inv;
            mn[h] = t[h]; mx[h] = t[h];
        }
#pragma unroll
        for (int off = 16; off; off >>= 1) {
#pragma unroll
            for (int h = 0; h < 8; h++) {
                mn[h] = fminf(mn[h], __shfl_xor_sync(0xffffffffu, mn[h], off));
                mx[h] = fmaxf(mx[h], __shfl_xor_sync(0xffffffffu, mx[h], off));
            }
        }
        if (lane == 0) {
#pragma unroll
            for (int h = 0; h < 8; h++) { s_mn[wig][h] = mn[h]; s_mx[wig][h] = mx[h]; }
        }
        __syncwarp();
        // combine the two warps' minmax via smem (both warps have written)
        __threadfence_block();
        // ensure both warps done: use bar across the 64 threads
        asm volatile("bar.sync 1, 64;" ::: "memory");
        float p = 0.f;
#pragma unroll
        for (int h = 0; h < 8; h++) {
            float lo = fminf(s_mn[0][h], s_mn[1][h]);
            float hi = fmaxf(s_mx[0][h], s_mx[1][h]);
            float o = fmaxf((t[h] - lo) / (hi - lo + EPSV), 0.f);
            p += o * Wout[node * 8 + h];
        }
        atomicAdd(&out[b], p);
    }
}

extern "C" void kernel_launch(void* const* d_in, const int* in_sizes, int n_in,
                              void* d_out, int out_size) {
    const float* x    = (const float*)d_in[0];
    const int*   e0s  = (const int*)d_in[1];
    const int*   e0d  = (const int*)d_in[2];
    const int*   e1s  = (const int*)d_in[3];
    const int*   e1d  = (const int*)d_in[4];
    const int*   e2s  = (const int*)d_in[5];
    const int*   e2d  = (const int*)d_in[6];
    const float* W0   = (const float*)d_in[7];
    const float* W1   = (const float*)d_in[8];
    const float* W2   = (const float*)d_in[9];
    const float* Wout = (const float*)d_in[10];
    const float* bout = (const float*)d_in[11];
    float* out = (float*)d_out;

    k_build<<<NB1, NT1>>>(x, e0s, e0d, e1s, e1d, e2s, e2d, bout, out);
    k_agg0<<<M0 / 8, 256>>>(W0);
    k_agg1<<<M1 / 4, 256>>>(W1);
    k_agg2out<<<M2, 256>>>(W2, Wout, out);
}